// round 10
// baseline (speedup 1.0000x reference)
#include <cuda_runtime.h>
#include <cuda_fp16.h>

// out[b,o] = max_k min(x[b,k], w[k,o])  (STE forward == hard max-min)
// x: [B,512] f32 uniform[0,1), w: [512,512] f32, out f32. B = 1024.
//
// R10: one fused kernel, hot loop entirely in smem.
// Block = 64 b-rows x 64 o-cols, 512 threads, grid 8x16 = 128 blocks (1
// wave). Stage w[:, o-tile] fp32->fp16 to smem once (coalesced stream).
// Per-row candidate lists (tier-1 x>=0.88 front / tier-2 [0.80,0.88) back
// of 112-entry slots; overflow -> exact row fallback). Hot loop per
// candidate per thread: broadcast LDS.64 + LDS.128 + 8 HMNMX2 covering 8
// outputs; quarter-warp == row-group -> conflict-free LDS phases.

#define KDIM 512
#define ODIM 512
#define BT   64
#define OT   64
#define NT   512
#define CROW 112          // tier1 count ~61 sd 7.4 -> P(overflow) ~ 0
#define CUT1 0.88f
#define CUT2 0.80f
#define EPS  1e-3f

#define WS_BYTES   (KDIM * OT * 2)                // 65536; w row k at byte k<<7
#define SMEM_BYTES (WS_BYTES + BT * CROW * 8)     // + 57344 = 122880

__global__ __launch_bounds__(NT, 1)
void maxmin_kernel(const float* __restrict__ x,
                   const float* __restrict__ w,
                   float* __restrict__ out, int B)
{
    extern __shared__ char smem[];
    uint2* cl = reinterpret_cast<uint2*>(smem + WS_BYTES);   // [BT][CROW]
    __shared__ int s_n1[BT], s_n2[BT];

    const int tid = threadIdx.x;
    const int oB  = blockIdx.x * OT;
    const int bB  = blockIdx.y * BT;
    const int r   = tid >> 3;          // row in b-tile (quarter-warp aligned)
    const int og  = tid & 7;           // owns outputs [oB+8*og, +8)

    if (tid < BT) { s_n1[tid] = 0; s_n2[tid] = 0; }
    __syncthreads();

    // ---- stage w tile fp32 -> fp16 smem (coalesced, no dependent stalls) ----
    {
        uint2* ws2 = reinterpret_cast<uint2*>(smem);
#pragma unroll
        for (int i = 0; i < (KDIM * OT / 4) / NT; i++) {   // 16 iters
            int idx = tid + i * NT;
            int k  = idx >> 4;
            int c4 = idx & 15;
            float4 v = *reinterpret_cast<const float4*>(
                w + (size_t)k * ODIM + oB + c4 * 4);
            __half2 h0 = __floats2half2_rn(v.x, v.y);
            __half2 h1 = __floats2half2_rn(v.z, v.w);
            uint2 pk;
            pk.x = *reinterpret_cast<unsigned*>(&h0);
            pk.y = *reinterpret_cast<unsigned*>(&h1);
            ws2[k * 16 + c4] = pk;                 // row k = 128B = 16 uint2
        }
    }

    // ---- per-row candidate selection (8 threads/row, coalesced) ----
    const bool rvalid = (bB + r) < B;
    if (rvalid) {
        const float4* xr4 =
            reinterpret_cast<const float4*>(x + (size_t)(bB + r) * KDIM);
#pragma unroll
        for (int i = 0; i < 16; i++) {
            float4 v = xr4[i * 8 + og];
            float e[4] = {v.x, v.y, v.z, v.w};
#pragma unroll
            for (int q = 0; q < 4; q++) {
                float xv = e[q];
                if (xv >= CUT2) {
                    int k = (i * 8 + og) * 4 + q;
                    __half   h  = __float2half_rn(xv);
                    __half2  h2 = __halves2half2(h, h);
                    uint2 ent;
                    ent.x = *reinterpret_cast<unsigned*>(&h2);
                    ent.y = (unsigned)(k << 7);    // byte offset of w row
                    if (xv >= CUT1) {
                        int p = atomicAdd(&s_n1[r], 1);
                        if (p < CROW) cl[r * CROW + p] = ent;
                    } else {
                        int p = atomicAdd(&s_n2[r], 1);
                        int pos = CROW - 1 - p;
                        if (pos >= 0) cl[r * CROW + pos] = ent;
                    }
                }
            }
        }
    }
    __syncthreads();

    const int c1n = s_n1[r];
    const int c2n = s_n2[r];
    const bool ovf = (c1n + c2n > CROW);     // slots may have collided

    __half2 a0 = __float2half2_rn(0.0f);     // inputs >= 0: 0 is a safe -inf
    __half2 a1 = a0, a2 = a0, a3 = a0;
    const uint2* myl = cl + r * CROW;

    // ---- tier-1 hot loop: all smem, ILP-4 batches ----
    if (rvalid && !ovf) {
        int t = 0;
        for (; t + 4 <= c1n; t += 4) {
            uint2 e0 = myl[t];
            uint2 e1 = myl[t + 1];
            uint2 e2 = myl[t + 2];
            uint2 e3 = myl[t + 3];
            uint4 w0 = *reinterpret_cast<const uint4*>(smem + e0.y + (og << 4));
            uint4 w1 = *reinterpret_cast<const uint4*>(smem + e1.y + (og << 4));
            uint4 w2 = *reinterpret_cast<const uint4*>(smem + e2.y + (og << 4));
            uint4 w3 = *reinterpret_cast<const uint4*>(smem + e3.y + (og << 4));
            __half2 xv;
            xv = *reinterpret_cast<__half2*>(&e0.x);
            a0 = __hmax2(a0, __hmin2(xv, *reinterpret_cast<__half2*>(&w0.x)));
            a1 = __hmax2(a1, __hmin2(xv, *reinterpret_cast<__half2*>(&w0.y)));
            a2 = __hmax2(a2, __hmin2(xv, *reinterpret_cast<__half2*>(&w0.z)));
            a3 = __hmax2(a3, __hmin2(xv, *reinterpret_cast<__half2*>(&w0.w)));
            xv = *reinterpret_cast<__half2*>(&e1.x);
            a0 = __hmax2(a0, __hmin2(xv, *reinterpret_cast<__half2*>(&w1.x)));
            a1 = __hmax2(a1, __hmin2(xv, *reinterpret_cast<__half2*>(&w1.y)));
            a2 = __hmax2(a2, __hmin2(xv, *reinterpret_cast<__half2*>(&w1.z)));
            a3 = __hmax2(a3, __hmin2(xv, *reinterpret_cast<__half2*>(&w1.w)));
            xv = *reinterpret_cast<__half2*>(&e2.x);
            a0 = __hmax2(a0, __hmin2(xv, *reinterpret_cast<__half2*>(&w2.x)));
            a1 = __hmax2(a1, __hmin2(xv, *reinterpret_cast<__half2*>(&w2.y)));
            a2 = __hmax2(a2, __hmin2(xv, *reinterpret_cast<__half2*>(&w2.z)));
            a3 = __hmax2(a3, __hmin2(xv, *reinterpret_cast<__half2*>(&w2.w)));
            xv = *reinterpret_cast<__half2*>(&e3.x);
            a0 = __hmax2(a0, __hmin2(xv, *reinterpret_cast<__half2*>(&w3.x)));
            a1 = __hmax2(a1, __hmin2(xv, *reinterpret_cast<__half2*>(&w3.y)));
            a2 = __hmax2(a2, __hmin2(xv, *reinterpret_cast<__half2*>(&w3.z)));
            a3 = __hmax2(a3, __hmin2(xv, *reinterpret_cast<__half2*>(&w3.w)));
        }
        for (; t < c1n; t++) {
            uint2 e = myl[t];
            uint4 wv = *reinterpret_cast<const uint4*>(smem + e.y + (og << 4));
            __half2 xv = *reinterpret_cast<__half2*>(&e.x);
            a0 = __hmax2(a0, __hmin2(xv, *reinterpret_cast<__half2*>(&wv.x)));
            a1 = __hmax2(a1, __hmin2(xv, *reinterpret_cast<__half2*>(&wv.y)));
            a2 = __hmax2(a2, __hmin2(xv, *reinterpret_cast<__half2*>(&wv.z)));
            a3 = __hmax2(a3, __hmin2(xv, *reinterpret_cast<__half2*>(&wv.w)));
        }
    }

    float rr[8];
    rr[0] = __low2float(a0); rr[1] = __high2float(a0);
    rr[2] = __low2float(a1); rr[3] = __high2float(a1);
    rr[4] = __low2float(a2); rr[5] = __high2float(a2);
    rr[6] = __low2float(a3); rr[7] = __high2float(a3);

    // ---- tier-2 extension (rare: ~0.5% of threads) ----
    float rmin = rr[0];
#pragma unroll
    for (int j = 1; j < 8; j++) rmin = fminf(rmin, rr[j]);

    if (rvalid && !ovf && rmin < CUT1 + EPS) {
#pragma unroll 1
        for (int t = 0; t < c2n; t++) {
            uint2 e = myl[CROW - 1 - t];
            uint4 wv = *reinterpret_cast<const uint4*>(smem + e.y + (og << 4));
            __half2 xv = *reinterpret_cast<__half2*>(&e.x);
            a0 = __hmax2(a0, __hmin2(xv, *reinterpret_cast<__half2*>(&wv.x)));
            a1 = __hmax2(a1, __hmin2(xv, *reinterpret_cast<__half2*>(&wv.y)));
            a2 = __hmax2(a2, __hmin2(xv, *reinterpret_cast<__half2*>(&wv.z)));
            a3 = __hmax2(a3, __hmin2(xv, *reinterpret_cast<__half2*>(&wv.w)));
        }
        rr[0] = __low2float(a0); rr[1] = __high2float(a0);
        rr[2] = __low2float(a1); rr[3] = __high2float(a1);
        rr[4] = __low2float(a2); rr[5] = __high2float(a2);
        rr[6] = __low2float(a3); rr[7] = __high2float(a3);
    }

    if (!rvalid) return;

    // ---- exact fp32 fallback (essentially never for uniform inputs) ----
#pragma unroll 1
    for (int j = 0; j < 8; j++) {
        if (ovf || rr[j] < CUT2 + EPS) {
            int o = oB + og * 8 + j;
            const float* xr = x + (size_t)(bB + r) * KDIM;
            float v = 0.0f;
#pragma unroll 1
            for (int k = 0; k < KDIM; k++)
                v = fmaxf(v, fminf(xr[k], w[(size_t)k * ODIM + o]));
            rr[j] = v;
        }
    }

    float4* op = reinterpret_cast<float4*>(
        out + (size_t)(bB + r) * ODIM + oB + og * 8);
    op[0] = make_float4(rr[0], rr[1], rr[2], rr[3]);
    op[1] = make_float4(rr[4], rr[5], rr[6], rr[7]);
}

extern "C" void kernel_launch(void* const* d_in, const int* in_sizes, int n_in,
                              void* d_out, int out_size)
{
    const float* x = (const float*)d_in[0];   // [B, 512]
    const float* w = (const float*)d_in[1];   // [512, 512]
    float* out = (float*)d_out;

    int B = in_sizes[0] / KDIM;               // 1024

    static int configured = 0;
    if (!configured) {
        cudaFuncSetAttribute(maxmin_kernel,
                             cudaFuncAttributeMaxDynamicSharedMemorySize,
                             SMEM_BYTES);
        configured = 1;
    }

    dim3 grid(ODIM / OT, (B + BT - 1) / BT);  // (8, 16) = 128 blocks
    maxmin_kernel<<<grid, NT, SMEM_BYTES>>>(x, w, out, B);
}

// round 11
// speedup vs baseline: 23.3202x; 23.3202x over previous
#include <cuda_runtime.h>
#include <cuda_fp16.h>

// out[b,o] = max_k min(x[b,k], w[k,o])  (STE forward == hard max-min)
// x: [B,512] f32 uniform[0,1), w: [512,512] f32, out f32. B = 1024.
//
// R11 = R10 with the overflow bug fixed: one fused kernel, hot loop all in
// smem. Block = 64 b x 64 o, 512 threads, 128 blocks (1 wave). Stage
// w[:, o-tile] fp32->fp16 once. Per-row candidate slots CROW=160 shared by
// tier-1 (x>=0.88, front) and tier-2 ([0.80,0.88), back): combined count
// 102 +- 9.1 -> P(overflow) ~ 8e-11 (R10 used 112 -> 15% overflow -> mass
// fallback, 549us). Candidate rows padded (+1 entry) to de-conflict the
// broadcast LDS.64 across the 4 row-groups of a warp.

#define KDIM 512
#define ODIM 512
#define BT   64
#define OT   64
#define NT   512
#define CROW 160          // shared tier1+tier2 slots; 161-entry padded stride
#define CSTRIDE (CROW + 1)
#define CUT1 0.88f
#define CUT2 0.80f
#define EPS  1e-3f

#define WS_BYTES   (KDIM * OT * 2)                   // 65536; w row k at byte k<<7
#define SMEM_BYTES (WS_BYTES + BT * CSTRIDE * 8)     // + 82432 = 147968

__global__ __launch_bounds__(NT, 1)
void maxmin_kernel(const float* __restrict__ x,
                   const float* __restrict__ w,
                   float* __restrict__ out, int B)
{
    extern __shared__ char smem[];
    uint2* cl = reinterpret_cast<uint2*>(smem + WS_BYTES);   // [BT][CSTRIDE]
    __shared__ int s_n1[BT], s_n2[BT];

    const int tid = threadIdx.x;
    const int oB  = blockIdx.x * OT;
    const int bB  = blockIdx.y * BT;
    const int r   = tid >> 3;          // row in b-tile (quarter-warp aligned)
    const int og  = tid & 7;           // owns outputs [oB+8*og, +8)

    if (tid < BT) { s_n1[tid] = 0; s_n2[tid] = 0; }
    __syncthreads();

    // ---- stage w tile fp32 -> fp16 smem (coalesced, no dependent stalls) ----
    {
        uint2* ws2 = reinterpret_cast<uint2*>(smem);
#pragma unroll
        for (int i = 0; i < (KDIM * OT / 4) / NT; i++) {   // 16 iters
            int idx = tid + i * NT;
            int k  = idx >> 4;
            int c4 = idx & 15;
            float4 v = *reinterpret_cast<const float4*>(
                w + (size_t)k * ODIM + oB + c4 * 4);
            __half2 h0 = __floats2half2_rn(v.x, v.y);
            __half2 h1 = __floats2half2_rn(v.z, v.w);
            uint2 pk;
            pk.x = *reinterpret_cast<unsigned*>(&h0);
            pk.y = *reinterpret_cast<unsigned*>(&h1);
            ws2[k * 16 + c4] = pk;                 // row k = 128B = 16 uint2
        }
    }

    // ---- per-row candidate selection (8 threads/row, coalesced) ----
    const bool rvalid = (bB + r) < B;
    if (rvalid) {
        const float4* xr4 =
            reinterpret_cast<const float4*>(x + (size_t)(bB + r) * KDIM);
#pragma unroll
        for (int i = 0; i < 16; i++) {
            float4 v = xr4[i * 8 + og];
            float e[4] = {v.x, v.y, v.z, v.w};
#pragma unroll
            for (int q = 0; q < 4; q++) {
                float xv = e[q];
                if (xv >= CUT2) {
                    int k = (i * 8 + og) * 4 + q;
                    __half   h  = __float2half_rn(xv);
                    __half2  h2 = __halves2half2(h, h);
                    uint2 ent;
                    ent.x = *reinterpret_cast<unsigned*>(&h2);
                    ent.y = (unsigned)(k << 7);    // byte offset of w row
                    if (xv >= CUT1) {
                        int p = atomicAdd(&s_n1[r], 1);
                        if (p < CROW) cl[r * CSTRIDE + p] = ent;
                    } else {
                        int p = atomicAdd(&s_n2[r], 1);
                        int pos = CROW - 1 - p;
                        if (pos >= 0) cl[r * CSTRIDE + pos] = ent;
                    }
                }
            }
        }
    }
    __syncthreads();

    const int c1n = s_n1[r];
    const int c2n = s_n2[r];
    const bool ovf = (c1n + c2n > CROW);     // slots collided: lists lossy

    __half2 a0 = __float2half2_rn(0.0f);     // inputs >= 0: 0 is a safe -inf
    __half2 a1 = a0, a2 = a0, a3 = a0;
    const uint2* myl = cl + r * CSTRIDE;

    // ---- tier-1 hot loop: all smem, ILP-4 batches ----
    if (rvalid && !ovf) {
        int t = 0;
        for (; t + 4 <= c1n; t += 4) {
            uint2 e0 = myl[t];
            uint2 e1 = myl[t + 1];
            uint2 e2 = myl[t + 2];
            uint2 e3 = myl[t + 3];
            uint4 w0 = *reinterpret_cast<const uint4*>(smem + e0.y + (og << 4));
            uint4 w1 = *reinterpret_cast<const uint4*>(smem + e1.y + (og << 4));
            uint4 w2 = *reinterpret_cast<const uint4*>(smem + e2.y + (og << 4));
            uint4 w3 = *reinterpret_cast<const uint4*>(smem + e3.y + (og << 4));
            __half2 xv;
            xv = *reinterpret_cast<__half2*>(&e0.x);
            a0 = __hmax2(a0, __hmin2(xv, *reinterpret_cast<__half2*>(&w0.x)));
            a1 = __hmax2(a1, __hmin2(xv, *reinterpret_cast<__half2*>(&w0.y)));
            a2 = __hmax2(a2, __hmin2(xv, *reinterpret_cast<__half2*>(&w0.z)));
            a3 = __hmax2(a3, __hmin2(xv, *reinterpret_cast<__half2*>(&w0.w)));
            xv = *reinterpret_cast<__half2*>(&e1.x);
            a0 = __hmax2(a0, __hmin2(xv, *reinterpret_cast<__half2*>(&w1.x)));
            a1 = __hmax2(a1, __hmin2(xv, *reinterpret_cast<__half2*>(&w1.y)));
            a2 = __hmax2(a2, __hmin2(xv, *reinterpret_cast<__half2*>(&w1.z)));
            a3 = __hmax2(a3, __hmin2(xv, *reinterpret_cast<__half2*>(&w1.w)));
            xv = *reinterpret_cast<__half2*>(&e2.x);
            a0 = __hmax2(a0, __hmin2(xv, *reinterpret_cast<__half2*>(&w2.x)));
            a1 = __hmax2(a1, __hmin2(xv, *reinterpret_cast<__half2*>(&w2.y)));
            a2 = __hmax2(a2, __hmin2(xv, *reinterpret_cast<__half2*>(&w2.z)));
            a3 = __hmax2(a3, __hmin2(xv, *reinterpret_cast<__half2*>(&w2.w)));
            xv = *reinterpret_cast<__half2*>(&e3.x);
            a0 = __hmax2(a0, __hmin2(xv, *reinterpret_cast<__half2*>(&w3.x)));
            a1 = __hmax2(a1, __hmin2(xv, *reinterpret_cast<__half2*>(&w3.y)));
            a2 = __hmax2(a2, __hmin2(xv, *reinterpret_cast<__half2*>(&w3.z)));
            a3 = __hmax2(a3, __hmin2(xv, *reinterpret_cast<__half2*>(&w3.w)));
        }
        for (; t < c1n; t++) {
            uint2 e = myl[t];
            uint4 wv = *reinterpret_cast<const uint4*>(smem + e.y + (og << 4));
            __half2 xv = *reinterpret_cast<__half2*>(&e.x);
            a0 = __hmax2(a0, __hmin2(xv, *reinterpret_cast<__half2*>(&wv.x)));
            a1 = __hmax2(a1, __hmin2(xv, *reinterpret_cast<__half2*>(&wv.y)));
            a2 = __hmax2(a2, __hmin2(xv, *reinterpret_cast<__half2*>(&wv.z)));
            a3 = __hmax2(a3, __hmin2(xv, *reinterpret_cast<__half2*>(&wv.w)));
        }
    }

    float rr[8];
    rr[0] = __low2float(a0); rr[1] = __high2float(a0);
    rr[2] = __low2float(a1); rr[3] = __high2float(a1);
    rr[4] = __low2float(a2); rr[5] = __high2float(a2);
    rr[6] = __low2float(a3); rr[7] = __high2float(a3);

    // ---- tier-2 extension (rare: ~0.35% of threads) ----
    float rmin = rr[0];
#pragma unroll
    for (int j = 1; j < 8; j++) rmin = fminf(rmin, rr[j]);

    if (rvalid && !ovf && rmin < CUT1 + EPS) {
#pragma unroll 1
        for (int t = 0; t < c2n; t++) {
            uint2 e = myl[CROW - 1 - t];
            uint4 wv = *reinterpret_cast<const uint4*>(smem + e.y + (og << 4));
            __half2 xv = *reinterpret_cast<__half2*>(&e.x);
            a0 = __hmax2(a0, __hmin2(xv, *reinterpret_cast<__half2*>(&wv.x)));
            a1 = __hmax2(a1, __hmin2(xv, *reinterpret_cast<__half2*>(&wv.y)));
            a2 = __hmax2(a2, __hmin2(xv, *reinterpret_cast<__half2*>(&wv.z)));
            a3 = __hmax2(a3, __hmin2(xv, *reinterpret_cast<__half2*>(&wv.w)));
        }
        rr[0] = __low2float(a0); rr[1] = __high2float(a0);
        rr[2] = __low2float(a1); rr[3] = __high2float(a1);
        rr[4] = __low2float(a2); rr[5] = __high2float(a2);
        rr[6] = __low2float(a3); rr[7] = __high2float(a3);
    }

    if (!rvalid) return;

    // ---- exact fp32 fallback (P ~ 1e-10 per output for uniform inputs) ----
#pragma unroll 1
    for (int j = 0; j < 8; j++) {
        if (ovf || rr[j] < CUT2 + EPS) {
            int o = oB + og * 8 + j;
            const float* xr = x + (size_t)(bB + r) * KDIM;
            float v = 0.0f;
#pragma unroll 1
            for (int k = 0; k < KDIM; k += 4) {
                float m0 = fminf(xr[k],     w[(size_t)(k)     * ODIM + o]);
                float m1 = fminf(xr[k + 1], w[(size_t)(k + 1) * ODIM + o]);
                float m2 = fminf(xr[k + 2], w[(size_t)(k + 2) * ODIM + o]);
                float m3 = fminf(xr[k + 3], w[(size_t)(k + 3) * ODIM + o]);
                v = fmaxf(v, fmaxf(fmaxf(m0, m1), fmaxf(m2, m3)));
            }
            rr[j] = v;
        }
    }

    float4* op = reinterpret_cast<float4*>(
        out + (size_t)(bB + r) * ODIM + oB + og * 8);
    op[0] = make_float4(rr[0], rr[1], rr[2], rr[3]);
    op[1] = make_float4(rr[4], rr[5], rr[6], rr[7]);
}

extern "C" void kernel_launch(void* const* d_in, const int* in_sizes, int n_in,
                              void* d_out, int out_size)
{
    const float* x = (const float*)d_in[0];   // [B, 512]
    const float* w = (const float*)d_in[1];   // [512, 512]
    float* out = (float*)d_out;

    int B = in_sizes[0] / KDIM;               // 1024

    cudaFuncSetAttribute(maxmin_kernel,
                         cudaFuncAttributeMaxDynamicSharedMemorySize,
                         SMEM_BYTES);

    dim3 grid(ODIM / OT, (B + BT - 1) / BT);  // (8, 16) = 128 blocks
    maxmin_kernel<<<grid, NT, SMEM_BYTES>>>(x, w, out, B);
}

// round 12
// speedup vs baseline: 27.8704x; 1.1951x over previous
#include <cuda_runtime.h>
#include <cuda_fp16.h>

// out[b,o] = max_k min(x[b,k], w[k,o])  (STE forward == hard max-min)
// x: [B,512] f32 uniform[0,1), w: [512,512] f32, out f32. B = 1024.
//
// Candidate algorithm (R6 base, measured best): per b-row, tier-1 cands
// x >= 0.875 (~64), tier-2 [0.78,0.875) for certificate failures (~3e-4),
// exact fp32 scan as last resort (any-distribution correctness).
// R12: software-pipelined hot loop — batch t+1's 8 LDS + 8 LDG issue
// before batch t's compute, keeping 8+ gathers in flight to cover L2/L1
// latency that R6 left exposed. c1 is zero-padded (zero candidates are
// harmless: min(0,w)=0 can't raise a max over nonnegative inputs).

#define KDIM 512
#define ODIM 512
#define O2   256          // half2 pairs along o; w row = 128 uint2
#define NT   128          // thread owns outputs [4t, 4t+4)
#define CUT1 0.875f
#define CUT2 0.78f
#define EPS  1e-3f
#define C1MAX 160         // tier1 ~64 +- 7.5 -> 12.8 sigma headroom
#define C2MAX 160         // tier2 ~49 +- 6.7

__device__ __half2 g_wh[KDIM * O2];   // [k][o2]; row k at uint2 index k*128

__global__ __launch_bounds__(512)
void packw_kernel(const float* __restrict__ w)
{
    int i = blockIdx.x * blockDim.x + threadIdx.x;   // 65536 float4 units
    float4 v = reinterpret_cast<const float4*>(w)[i];
    __half2 h0 = __floats2half2_rn(v.x, v.y);
    __half2 h1 = __floats2half2_rn(v.z, v.w);
    uint2 pk;
    pk.x = *reinterpret_cast<unsigned*>(&h0);
    pk.y = *reinterpret_cast<unsigned*>(&h1);
    reinterpret_cast<uint2*>(g_wh)[i] = pk;
}

__global__ __launch_bounds__(NT)
void maxmin_kernel(const float* __restrict__ x,
                   const float* __restrict__ w,
                   float* __restrict__ out)
{
    __shared__ float xs[KDIM];
    __shared__ uint2 c1[C1MAX];       // {half2-splat(x) bits, k*128}
    __shared__ uint2 c2[C2MAX];
    __shared__ int   s_n1, s_n2, s_ovf;

    const int b   = blockIdx.x;
    const int tid = threadIdx.x;      // owns outputs 4*tid .. 4*tid+3

    if (tid == 0) { s_n1 = 0; s_n2 = 0; s_ovf = 0; }
    // zero c1 so zero-padded batches are harmless
    c1[tid] = make_uint2(0u, 0u);
    if (tid + NT < C1MAX) c1[tid + NT] = make_uint2(0u, 0u);
    __syncthreads();

    // ---- stage x row (fp32, for fallback) + threshold selection ----
    {
        float4 v = reinterpret_cast<const float4*>(x + (size_t)b * KDIM)[tid];
        reinterpret_cast<float4*>(xs)[tid] = v;
        float e[4] = {v.x, v.y, v.z, v.w};
#pragma unroll
        for (int q = 0; q < 4; q++) {
            float xv = e[q];
            if (xv >= CUT2) {
                int k = tid * 4 + q;
                __half   h  = __float2half_rn(xv);
                __half2  h2 = __halves2half2(h, h);
                unsigned hb = *reinterpret_cast<const unsigned*>(&h2);
                if (xv >= CUT1) {
                    int p = atomicAdd(&s_n1, 1);
                    if (p < C1MAX) c1[p] = make_uint2(hb, (unsigned)(k * 128));
                    else           s_ovf = 1;
                } else {
                    int p = atomicAdd(&s_n2, 1);
                    if (p < C2MAX) c2[p] = make_uint2(hb, (unsigned)(k * 128));
                    else           s_ovf = 1;
                }
            }
        }
    }
    __syncthreads();

    const int cnt1 = s_n1;
    const int cnt2 = (s_n2 < C2MAX) ? s_n2 : C2MAX;
    const int ovf  = s_ovf;
    const int n1p  = (cnt1 + 7) & ~7;       // zero-padded length, <= C1MAX

    const uint2* wu = reinterpret_cast<const uint2*>(g_wh);

    __half2 a0 = __float2half2_rn(0.0f);    // inputs >= 0: 0 is a safe -inf
    __half2 a1 = a0;

    if (!ovf && n1p > 0) {
        // ---- 2-deep pipelined hot loop: prefetch batch t+8 during batch t ----
        unsigned xb[8];
        uint2    wv[8];
#pragma unroll
        for (int u = 0; u < 8; u++) {       // prologue: batch 0 in flight
            uint2 c = c1[u];
            xb[u] = c.x;
            wv[u] = wu[c.y + tid];
        }
        for (int t = 8; t < n1p; t += 8) {
            unsigned xb2[8];
            uint2    wv2[8];
#pragma unroll
            for (int u = 0; u < 8; u++) {   // issue next batch's loads first
                uint2 c = c1[t + u];
                xb2[u] = c.x;
                wv2[u] = wu[c.y + tid];
            }
#pragma unroll
            for (int u = 0; u < 8; u++) {   // compute current batch
                __half2 xv = *reinterpret_cast<__half2*>(&xb[u]);
                a0 = __hmax2(a0, __hmin2(xv, *reinterpret_cast<__half2*>(&wv[u].x)));
                a1 = __hmax2(a1, __hmin2(xv, *reinterpret_cast<__half2*>(&wv[u].y)));
            }
#pragma unroll
            for (int u = 0; u < 8; u++) { xb[u] = xb2[u]; wv[u] = wv2[u]; }
        }
#pragma unroll
        for (int u = 0; u < 8; u++) {       // epilogue batch
            __half2 xv = *reinterpret_cast<__half2*>(&xb[u]);
            a0 = __hmax2(a0, __hmin2(xv, *reinterpret_cast<__half2*>(&wv[u].x)));
            a1 = __hmax2(a1, __hmin2(xv, *reinterpret_cast<__half2*>(&wv[u].y)));
        }
    }

    float r[4];
    r[0] = __low2float(a0); r[1] = __high2float(a0);
    r[2] = __low2float(a1); r[3] = __high2float(a1);

    // ---- tier-2 extension (rare; any of 4 outputs failing certificate) ----
    bool fail1 = false;
#pragma unroll
    for (int j = 0; j < 4; j++) fail1 |= (r[j] < CUT1 + EPS);

    if (!ovf && fail1) {
#pragma unroll 1
        for (int t = 0; t < cnt2; t++) {
            uint2 c = c2[t];
            uint2 wv = wu[c.y + tid];
            __half2 xv = *reinterpret_cast<__half2*>(&c.x);
            a0 = __hmax2(a0, __hmin2(xv, *reinterpret_cast<__half2*>(&wv.x)));
            a1 = __hmax2(a1, __hmin2(xv, *reinterpret_cast<__half2*>(&wv.y)));
        }
        r[0] = __low2float(a0); r[1] = __high2float(a0);
        r[2] = __low2float(a1); r[3] = __high2float(a1);
    }

    // ---- exact fp32 fallback (essentially never for uniform inputs) ----
#pragma unroll 1
    for (int j = 0; j < 4; j++) {
        if (ovf || r[j] < CUT2 + EPS) {
            int o = tid * 4 + j;
            float v = 0.0f;
#pragma unroll 1
            for (int k = 0; k < KDIM; k += 4) {
                float m0 = fminf(xs[k],     w[(size_t)(k)     * ODIM + o]);
                float m1 = fminf(xs[k + 1], w[(size_t)(k + 1) * ODIM + o]);
                float m2 = fminf(xs[k + 2], w[(size_t)(k + 2) * ODIM + o]);
                float m3 = fminf(xs[k + 3], w[(size_t)(k + 3) * ODIM + o]);
                v = fmaxf(v, fmaxf(fmaxf(m0, m1), fmaxf(m2, m3)));
            }
            r[j] = v;
        }
    }

    reinterpret_cast<float4*>(out + (size_t)b * ODIM)[tid] =
        make_float4(r[0], r[1], r[2], r[3]);
}

extern "C" void kernel_launch(void* const* d_in, const int* in_sizes, int n_in,
                              void* d_out, int out_size)
{
    const float* x = (const float*)d_in[0];   // [B, 512]
    const float* w = (const float*)d_in[1];   // [512, 512]
    float* out = (float*)d_out;

    int B = in_sizes[0] / KDIM;               // 1024

    packw_kernel<<<128, 512>>>(w);            // 65536 threads, 1 float4 each
    maxmin_kernel<<<B, NT>>>(x, w, out);
}